// round 1
// baseline (speedup 1.0000x reference)
#include <cuda_runtime.h>

#define BSZ 4096
#define CSZ 1024
#define NT  32          // 4096 / 128 tiles
#define HALF_N 8388608u // (4096*4096)/2

// ---------------- scratch (no allocations allowed) ----------------
__device__ float               g_sq[BSZ];
__device__ float               g_row_ce[BSZ];
__device__ float               g_row_nce[BSZ];
__device__ unsigned long long  g_hard_key[BSZ];
__device__ int                 g_rand_idx[BSZ];

// orderable encoding of float for integer max
__device__ __forceinline__ unsigned int f2o(float f) {
    unsigned int u = __float_as_uint(f);
    return (u & 0x80000000u) ? ~u : (u | 0x80000000u);
}

// JAX Threefry-2x32 (20 rounds), key = (0, 42) for jax.random.key(42)
__device__ __forceinline__ void threefry2x32(unsigned int k0, unsigned int k1,
                                             unsigned int x0, unsigned int x1,
                                             unsigned int& o0, unsigned int& o1) {
    unsigned int ks2 = k0 ^ k1 ^ 0x1BD11BDAu;
#define TF_RND(r) { x0 += x1; x1 = (x1 << (r)) | (x1 >> (32 - (r))); x1 ^= x0; }
    x0 += k0;  x1 += k1;
    TF_RND(13) TF_RND(15) TF_RND(26) TF_RND(6)
    x0 += k1;  x1 += ks2 + 1u;
    TF_RND(17) TF_RND(29) TF_RND(16) TF_RND(24)
    x0 += ks2; x1 += k0 + 2u;
    TF_RND(13) TF_RND(15) TF_RND(26) TF_RND(6)
    x0 += k0;  x1 += k1 + 3u;
    TF_RND(17) TF_RND(29) TF_RND(16) TF_RND(24)
    x0 += k1;  x1 += ks2 + 4u;
    TF_RND(13) TF_RND(15) TF_RND(26) TF_RND(6)
    x0 += ks2; x1 += k0 + 5u;
#undef TF_RND
    o0 = x0; o1 = x1;
}

// ---------------- K0: init atomics ----------------
__global__ void k_init() {
    int i = blockIdx.x * blockDim.x + threadIdx.x;
    if (i < BSZ) g_hard_key[i] = 0ull;
}

// ---------------- K1: per-row sq, logsumexp, CE term ----------------
__global__ void k_row_stats(const float* __restrict__ outs,
                            const int* __restrict__ label) {
    int row = blockIdx.x;
    int t = threadIdx.x;            // 256 threads, 4 floats each
    float4 v = ((const float4*)(outs + (size_t)row * CSZ))[t];
    float mx = fmaxf(fmaxf(v.x, v.y), fmaxf(v.z, v.w));
    #pragma unroll
    for (int o = 16; o; o >>= 1) mx = fmaxf(mx, __shfl_xor_sync(0xFFFFFFFFu, mx, o));
    __shared__ float sm[8];
    int w = t >> 5, l = t & 31;
    if (l == 0) sm[w] = mx;
    __syncthreads();
    if (t == 0) {
        float m = sm[0];
        #pragma unroll
        for (int q = 1; q < 8; q++) m = fmaxf(m, sm[q]);
        sm[0] = m;
    }
    __syncthreads();
    mx = sm[0];

    float es = expf(v.x - mx) + expf(v.y - mx) + expf(v.z - mx) + expf(v.w - mx);
    float qs = v.x * v.x + v.y * v.y + v.z * v.z + v.w * v.w;
    #pragma unroll
    for (int o = 16; o; o >>= 1) {
        es += __shfl_xor_sync(0xFFFFFFFFu, es, o);
        qs += __shfl_xor_sync(0xFFFFFFFFu, qs, o);
    }
    __shared__ float se[8], sq2[8];
    if (l == 0) { se[w] = es; sq2[w] = qs; }
    __syncthreads();
    if (t == 0) {
        float E = 0.f, Q = 0.f;
        #pragma unroll
        for (int q = 0; q < 8; q++) { E += se[q]; Q += sq2[q]; }
        int lab = label[row];
        g_row_ce[row] = logf(E) + mx - outs[(size_t)row * CSZ + lab];
        g_sq[row] = Q;
    }
}

// ---------------- K2: symmetric Gram + hard-negative argmax ----------------
// block pair (bi<=bj), 128x128 tile, 8x8 per thread, K-chunk=8 with prefetch.
__global__ __launch_bounds__(256)
void k_hard(const float* __restrict__ X, const int* __restrict__ label) {
    // map linear block id -> upper-triangular tile pair
    int p = blockIdx.x;
    int bi = 0, rem = p, width = NT;
    while (rem >= width) { rem -= width; bi++; width--; }
    int bj = bi + rem;
    int i0 = bi * 128, j0 = bj * 128;

    __shared__ float As[8][128];
    __shared__ float Bs[8][128];

    int t = threadIdx.x;
    int ty = t >> 4, tx = t & 15;

    float acc[8][8];
    #pragma unroll
    for (int m = 0; m < 8; m++)
        #pragma unroll
        for (int n = 0; n < 8; n++) acc[m][n] = 0.f;

    int lrow = t >> 1;            // 0..127
    int lk   = (t & 1) * 4;       // 0 or 4
    const float* Abase = X + (size_t)(i0 + lrow) * CSZ + lk;
    const float* Bbase = X + (size_t)(j0 + lrow) * CSZ + lk;

    float4 av = *(const float4*)(Abase);
    float4 bv = *(const float4*)(Bbase);

    for (int kk = 0; kk < CSZ; kk += 8) {
        __syncthreads();
        As[lk + 0][lrow] = av.x; As[lk + 1][lrow] = av.y;
        As[lk + 2][lrow] = av.z; As[lk + 3][lrow] = av.w;
        Bs[lk + 0][lrow] = bv.x; Bs[lk + 1][lrow] = bv.y;
        Bs[lk + 2][lrow] = bv.z; Bs[lk + 3][lrow] = bv.w;
        __syncthreads();
        if (kk + 8 < CSZ) {
            av = *(const float4*)(Abase + kk + 8);
            bv = *(const float4*)(Bbase + kk + 8);
        }
        #pragma unroll
        for (int k = 0; k < 8; k++) {
            float4 a0 = *(const float4*)&As[k][ty * 8];
            float4 a1 = *(const float4*)&As[k][ty * 8 + 4];
            float4 b0 = *(const float4*)&Bs[k][tx * 8];
            float4 b1 = *(const float4*)&Bs[k][tx * 8 + 4];
            float a[8] = {a0.x, a0.y, a0.z, a0.w, a1.x, a1.y, a1.z, a1.w};
            float b[8] = {b0.x, b0.y, b0.z, b0.w, b1.x, b1.y, b1.z, b1.w};
            #pragma unroll
            for (int m = 0; m < 8; m++)
                #pragma unroll
                for (int n = 0; n < 8; n++)
                    acc[m][n] += a[m] * b[n];
        }
    }

    // ---- epilogue: masked argmax of  sq[col] - 2*dot  per row ----
    __shared__ float s_sqi[128], s_sqj[128];
    __shared__ int   s_li[128], s_lj[128];
    __shared__ unsigned long long red[128][17];  // +1 pad vs bank conflicts
    __syncthreads();
    if (t < 128) {
        s_sqi[t] = g_sq[i0 + t]; s_sqj[t] = g_sq[j0 + t];
        s_li[t]  = label[i0 + t]; s_lj[t] = label[j0 + t];
    }
    __syncthreads();

    // epilogue A: rows from i-tile, candidates from j-tile
    #pragma unroll
    for (int m = 0; m < 8; m++) {
        int il = ty * 8 + m;
        int li = s_li[il];
        unsigned long long best = 0ull;
        #pragma unroll
        for (int n = 0; n < 8; n++) {
            int jl = tx * 8 + n;
            if (s_lj[jl] != li) {
                float v = s_sqj[jl] - 2.0f * acc[m][n];
                unsigned long long key =
                    ((unsigned long long)f2o(v) << 32) |
                    (unsigned long long)(0xFFFFFFFFu - (unsigned)(j0 + jl));
                if (key > best) best = key;
            }
        }
        red[il][tx] = best;
    }
    __syncthreads();
    if (t < 128) {
        unsigned long long best = red[t][0];
        #pragma unroll
        for (int q = 1; q < 16; q++) if (red[t][q] > best) best = red[t][q];
        if (best) atomicMax(&g_hard_key[i0 + t], best);
    }

    if (bi != bj) {
        __syncthreads();
        // epilogue B: rows from j-tile, candidates from i-tile (transpose reuse)
        #pragma unroll
        for (int n = 0; n < 8; n++) {
            int jl = tx * 8 + n;
            int lj = s_lj[jl];
            unsigned long long best = 0ull;
            #pragma unroll
            for (int m = 0; m < 8; m++) {
                int il = ty * 8 + m;
                if (s_li[il] != lj) {
                    float v = s_sqi[il] - 2.0f * acc[m][n];
                    unsigned long long key =
                        ((unsigned long long)f2o(v) << 32) |
                        (unsigned long long)(0xFFFFFFFFu - (unsigned)(i0 + il));
                    if (key > best) best = key;
                }
            }
            red[jl][ty] = best;
        }
        __syncthreads();
        if (t < 128) {
            unsigned long long best = red[t][0];
            #pragma unroll
            for (int q = 1; q < 16; q++) if (red[t][q] > best) best = red[t][q];
            if (best) atomicMax(&g_hard_key[j0 + t], best);
        }
    }
}

// ---------------- K3: JAX gumbel argmax (integer, monotone shortcut) -------
// Row pair (i, i+2048): bits[i*B+j] = out0, bits[(i+2048)*B+j] = out1 of
// threefry(key, (i*B+j, i*B+j+HALF_N)).  argmax(gumbel) == argmax(bits>>9),
// first occurrence on ties.
__global__ void k_rand(const int* __restrict__ label) {
    int i = blockIdx.x;                 // 0..2047
    int t = threadIdx.x;                // 256
    __shared__ int slab[BSZ];           // 16 KB
    for (int j = t; j < BSZ; j += 256) slab[j] = label[j];
    __syncthreads();
    int li0 = slab[i], li1 = slab[i + 2048];

    unsigned long long b0 = 0ull, b1 = 0ull;
    for (int j = t; j < BSZ; j += 256) {
        unsigned int m0 = (unsigned)(i * BSZ + j);
        unsigned int o0, o1;
        threefry2x32(0u, 42u, m0, m0 + HALF_N, o0, o1);
        unsigned long long tb = (unsigned long long)(0xFFFFFFFFu - (unsigned)j);
        if (slab[j] != li0) {
            unsigned long long key = ((unsigned long long)(o0 >> 9) << 32) | tb;
            if (key > b0) b0 = key;
        }
        if (slab[j] != li1) {
            unsigned long long key = ((unsigned long long)(o1 >> 9) << 32) | tb;
            if (key > b1) b1 = key;
        }
    }
    __shared__ unsigned long long r0[256], r1[256];
    r0[t] = b0; r1[t] = b1;
    __syncthreads();
    for (int s = 128; s; s >>= 1) {
        if (t < s) {
            if (r0[t + s] > r0[t]) r0[t] = r0[t + s];
            if (r1[t + s] > r1[t]) r1[t] = r1[t + s];
        }
        __syncthreads();
    }
    if (t == 0) {
        g_rand_idx[i]        = (int)(0xFFFFFFFFu - (unsigned)(r0[0] & 0xFFFFFFFFu)) & (BSZ - 1);
        g_rand_idx[i + 2048] = (int)(0xFFFFFFFFu - (unsigned)(r1[0] & 0xFFFFFFFFu)) & (BSZ - 1);
    }
}

// ---------------- K4: gathered dots + 3-way log-softmax -------------------
__global__ void k_nce(const float* __restrict__ outs,
                      const float* __restrict__ centers,
                      const int* __restrict__ label) {
    int i = blockIdx.x;
    int t = threadIdx.x;                 // 128
    int lab = label[i];
    unsigned long long hk = g_hard_key[i];
    int hidx = (int)(0xFFFFFFFFu - (unsigned)(hk & 0xFFFFFFFFu)) & (BSZ - 1);
    int ridx = g_rand_idx[i] & (BSZ - 1);

    const float4* xi = (const float4*)(outs + (size_t)i * CSZ);
    const float4* pc = (const float4*)(centers + (size_t)lab * CSZ);
    const float4* xr = (const float4*)(outs + (size_t)ridx * CSZ);
    const float4* xh = (const float4*)(outs + (size_t)hidx * CSZ);

    float sp = 0.f, sr = 0.f, sh = 0.f;
    #pragma unroll
    for (int q = t; q < CSZ / 4; q += 128) {
        float4 a = xi[q]; float4 p = pc[q]; float4 r = xr[q]; float4 h = xh[q];
        sp += a.x * p.x + a.y * p.y + a.z * p.z + a.w * p.w;
        sr += a.x * r.x + a.y * r.y + a.z * r.z + a.w * r.w;
        sh += a.x * h.x + a.y * h.y + a.z * h.z + a.w * h.w;
    }
    #pragma unroll
    for (int o = 16; o; o >>= 1) {
        sp += __shfl_xor_sync(0xFFFFFFFFu, sp, o);
        sr += __shfl_xor_sync(0xFFFFFFFFu, sr, o);
        sh += __shfl_xor_sync(0xFFFFFFFFu, sh, o);
    }
    __shared__ float ap[4], ar[4], ah[4];
    int w = t >> 5, l = t & 31;
    if (l == 0) { ap[w] = sp; ar[w] = sr; ah[w] = sh; }
    __syncthreads();
    if (t == 0) {
        float P = ap[0] + ap[1] + ap[2] + ap[3];
        float R = ar[0] + ar[1] + ar[2] + ar[3];
        float H = ah[0] + ah[1] + ah[2] + ah[3];
        float m = fmaxf(P, fmaxf(R, H));
        float lse = logf(expf(P - m) + expf(R - m) + expf(H - m)) + m;
        g_row_nce[i] = lse - P;
    }
}

// ---------------- K5: final deterministic reduce --------------------------
__global__ void k_final(float* __restrict__ out) {
    int t = threadIdx.x;                 // 256
    float a = 0.f, b = 0.f;
    for (int i = t; i < BSZ; i += 256) { a += g_row_ce[i]; b += g_row_nce[i]; }
    __shared__ float s1[256], s2[256];
    s1[t] = a; s2[t] = b;
    __syncthreads();
    for (int s = 128; s; s >>= 1) {
        if (t < s) { s1[t] += s1[t + s]; s2[t] += s2[t + s]; }
        __syncthreads();
    }
    if (t == 0)
        out[0] = s1[0] / (float)BSZ + 0.1f * (s2[0] / (float)BSZ);
}

// ---------------- launch ---------------------------------------------------
extern "C" void kernel_launch(void* const* d_in, const int* in_sizes, int n_in,
                              void* d_out, int out_size) {
    const float* outs    = (const float*)d_in[0];
    const float* centers = (const float*)d_in[1];
    const int*   label   = (const int*)d_in[2];

    k_init<<<(BSZ + 255) / 256, 256>>>();
    k_row_stats<<<BSZ, 256>>>(outs, label);
    k_rand<<<BSZ / 2, 256>>>(label);
    k_hard<<<NT * (NT + 1) / 2, 256>>>(outs, label);
    k_nce<<<BSZ, 128>>>(outs, centers, label);
    k_final<<<1, 256>>>((float*)d_out);
}

// round 3
// speedup vs baseline: 3.8441x; 3.8441x over previous
#include <cuda_runtime.h>
#include <cuda_bf16.h>
#include <cstdint>

#define BSZ 4096
#define CSZ 1024
#define NT  32          // 4096 / 128 tiles
#define HALF_N 8388608u // (4096*4096)/2
#define NCHUNK 16       // K = 1024 bf16 / 64 per chunk
#define STAGES 3

// ---------------- scratch (no allocations allowed) ----------------
__device__ float               g_sq[BSZ];
__device__ float               g_row_ce[BSZ];
__device__ float               g_row_nce[BSZ];
__device__ unsigned long long  g_hard_key[BSZ];
__device__ int                 g_rand_idx[BSZ];
__device__ __nv_bfloat16       g_xb16[BSZ * CSZ];   // bf16 copy of outs, 8 MB

// orderable encoding of float for integer max
__device__ __forceinline__ unsigned int f2o(float f) {
    unsigned int u = __float_as_uint(f);
    return (u & 0x80000000u) ? ~u : (u | 0x80000000u);
}

// ---------------- warp MMA helpers (non-'a' PTX only) ----------------
__device__ __forceinline__ uint32_t smem_u32(const void* p) {
    uint32_t a;
    asm("{ .reg .u64 t; cvta.to.shared.u64 t, %1; cvt.u32.u64 %0, t; }" : "=r"(a) : "l"(p));
    return a;
}
__device__ __forceinline__ void ldm_x4(uint32_t* r, uint32_t addr) {
    asm volatile("ldmatrix.sync.aligned.m8n8.x4.shared.b16 {%0,%1,%2,%3}, [%4];"
                 : "=r"(r[0]), "=r"(r[1]), "=r"(r[2]), "=r"(r[3]) : "r"(addr));
}
__device__ __forceinline__ void mma16816(float* c, const uint32_t* a,
                                         uint32_t b0, uint32_t b1) {
    asm volatile("mma.sync.aligned.m16n8k16.row.col.f32.bf16.bf16.f32 "
                 "{%0,%1,%2,%3}, {%4,%5,%6,%7}, {%8,%9}, {%0,%1,%2,%3};"
                 : "+f"(c[0]), "+f"(c[1]), "+f"(c[2]), "+f"(c[3])
                 : "r"(a[0]), "r"(a[1]), "r"(a[2]), "r"(a[3]), "r"(b0), "r"(b1));
}
#define CP_ASYNC16(dst, src) \
    asm volatile("cp.async.cg.shared.global [%0], [%1], 16;" :: "r"(dst), "l"(src))
#define CP_COMMIT() asm volatile("cp.async.commit_group;")
#define CP_WAIT2()  asm volatile("cp.async.wait_group 2;" ::: "memory")

// JAX Threefry-2x32 (20 rounds), key = (0, 42) for jax.random.key(42)
__device__ __forceinline__ void threefry2x32(unsigned int k0, unsigned int k1,
                                             unsigned int x0, unsigned int x1,
                                             unsigned int& o0, unsigned int& o1) {
    unsigned int ks2 = k0 ^ k1 ^ 0x1BD11BDAu;
#define TF_RND(r) { x0 += x1; x1 = (x1 << (r)) | (x1 >> (32 - (r))); x1 ^= x0; }
    x0 += k0;  x1 += k1;
    TF_RND(13) TF_RND(15) TF_RND(26) TF_RND(6)
    x0 += k1;  x1 += ks2 + 1u;
    TF_RND(17) TF_RND(29) TF_RND(16) TF_RND(24)
    x0 += ks2; x1 += k0 + 2u;
    TF_RND(13) TF_RND(15) TF_RND(26) TF_RND(6)
    x0 += k0;  x1 += k1 + 3u;
    TF_RND(17) TF_RND(29) TF_RND(16) TF_RND(24)
    x0 += k1;  x1 += ks2 + 4u;
    TF_RND(13) TF_RND(15) TF_RND(26) TF_RND(6)
    x0 += ks2; x1 += k0 + 5u;
#undef TF_RND
    o0 = x0; o1 = x1;
}

// ---------------- K0: init atomics ----------------
__global__ void k_init() {
    int i = blockIdx.x * blockDim.x + threadIdx.x;
    if (i < BSZ) g_hard_key[i] = 0ull;
}

// ---------------- K0b: fp32 -> bf16 copy ----------------
__global__ void k_cvt(const float* __restrict__ outs) {
    int i = blockIdx.x * blockDim.x + threadIdx.x;   // per float4
    float4 v = ((const float4*)outs)[i];
    __nv_bfloat162 p0 = __floats2bfloat162_rn(v.x, v.y);
    __nv_bfloat162 p1 = __floats2bfloat162_rn(v.z, v.w);
    uint2 o;
    o.x = *(unsigned*)&p0;
    o.y = *(unsigned*)&p1;
    ((uint2*)g_xb16)[i] = o;
}

// ---------------- K1: per-row sq, logsumexp, CE term ----------------
__global__ void k_row_stats(const float* __restrict__ outs,
                            const int* __restrict__ label) {
    int row = blockIdx.x;
    int t = threadIdx.x;            // 256 threads, 4 floats each
    float4 v = ((const float4*)(outs + (size_t)row * CSZ))[t];
    float mx = fmaxf(fmaxf(v.x, v.y), fmaxf(v.z, v.w));
    #pragma unroll
    for (int o = 16; o; o >>= 1) mx = fmaxf(mx, __shfl_xor_sync(0xFFFFFFFFu, mx, o));
    __shared__ float sm[8];
    int w = t >> 5, l = t & 31;
    if (l == 0) sm[w] = mx;
    __syncthreads();
    if (t == 0) {
        float m = sm[0];
        #pragma unroll
        for (int q = 1; q < 8; q++) m = fmaxf(m, sm[q]);
        sm[0] = m;
    }
    __syncthreads();
    mx = sm[0];

    float es = expf(v.x - mx) + expf(v.y - mx) + expf(v.z - mx) + expf(v.w - mx);
    float qs = v.x * v.x + v.y * v.y + v.z * v.z + v.w * v.w;
    #pragma unroll
    for (int o = 16; o; o >>= 1) {
        es += __shfl_xor_sync(0xFFFFFFFFu, es, o);
        qs += __shfl_xor_sync(0xFFFFFFFFu, qs, o);
    }
    __shared__ float se[8], sq2[8];
    if (l == 0) { se[w] = es; sq2[w] = qs; }
    __syncthreads();
    if (t == 0) {
        float E = 0.f, Q = 0.f;
        #pragma unroll
        for (int q = 0; q < 8; q++) { E += se[q]; Q += sq2[q]; }
        int lab = label[row];
        g_row_ce[row] = logf(E) + mx - outs[(size_t)row * CSZ + lab];
        g_sq[row] = Q;
    }
}

// ---------------- K2: symmetric Gram via bf16 HMMA + hard-negative argmax --
// 128x128 tile per CTA pair (bi<=bj); K=1024 bf16, 3-stage cp.async pipeline.
// 8 warps: warp_m = wid&1 (64 rows), warp_n = wid>>1 (32 cols).
extern __shared__ __align__(1024) unsigned char dsm[];  // 96 KB

__global__ __launch_bounds__(256, 2)
void k_hard_hmma(const int* __restrict__ label) {
    int p = blockIdx.x;
    int bi = 0, rem = p, width = NT;
    while (rem >= width) { rem -= width; bi++; width--; }
    int bj = bi + rem;
    int i0 = bi * 128, j0 = bj * 128;

    __shared__ int   s_li[128], s_lj[128];
    __shared__ float s_sqi[128], s_sqj[128];

    int t = threadIdx.x;
    int lane = t & 31, wid = t >> 5;
    int wm = wid & 1, wn = wid >> 1;
    uint32_t dynb = smem_u32(dsm);

    if (t < 128) {
        s_li[t] = label[i0 + t]; s_sqi[t] = g_sq[i0 + t];
        s_lj[t] = label[j0 + t]; s_sqj[t] = g_sq[j0 + t];
    }

    // cp.async assignment: thread -> (row, 4x16B segs)
    int lrow = t >> 1;
    int lseg = (t & 1) * 4;
    const char* gA = (const char*)g_xb16 + (size_t)(i0 + lrow) * 2048 + lseg * 16;
    const char* gB = (const char*)g_xb16 + (size_t)(j0 + lrow) * 2048 + lseg * 16;
    uint32_t dA[4], dB[4];
    #pragma unroll
    for (int q = 0; q < 4; q++) {
        unsigned off = (unsigned)lrow * 128u + (unsigned)(lseg + q) * 16u;
        unsigned sw = off ^ ((off >> 3) & 0x70u);
        dA[q] = sw; dB[q] = sw + 16384u;
    }

    // preload 3 chunks
    #pragma unroll
    for (int s = 0; s < STAGES; s++) {
        uint32_t sb = dynb + s * 32768u;
        #pragma unroll
        for (int q = 0; q < 4; q++) {
            CP_ASYNC16(sb + dA[q], gA + s * 128 + q * 16);
            CP_ASYNC16(sb + dB[q], gB + s * 128 + q * 16);
        }
        CP_COMMIT();
    }

    float acc[4][4][4];
    #pragma unroll
    for (int a = 0; a < 4; a++)
        #pragma unroll
        for (int b = 0; b < 4; b++)
            #pragma unroll
            for (int c = 0; c < 4; c++) acc[a][b][c] = 0.f;

    int rowA0 = wm * 64 + (lane & 15);
    int rowB0 = wn * 32 + (lane & 15);
    int kb_l  = (lane & 16);          // 0 or 16 bytes

    for (int c = 0; c < NCHUNK; c++) {
        CP_WAIT2();
        __syncthreads();
        uint32_t sb = dynb + (uint32_t)(c % STAGES) * 32768u;
        #pragma unroll
        for (int ks = 0; ks < 4; ks++) {
            uint32_t afr[4][4], bfr[2][4];
            #pragma unroll
            for (int mi = 0; mi < 4; mi++) {
                unsigned off = (unsigned)(rowA0 + mi * 16) * 128u + (unsigned)(ks * 32 + kb_l);
                unsigned sw = off ^ ((off >> 3) & 0x70u);
                ldm_x4(afr[mi], sb + sw);
            }
            #pragma unroll
            for (int n2 = 0; n2 < 2; n2++) {
                unsigned off = (unsigned)(rowB0 + n2 * 16) * 128u + (unsigned)(ks * 32 + kb_l);
                unsigned sw = off ^ ((off >> 3) & 0x70u);
                ldm_x4(bfr[n2], sb + 16384u + sw);
            }
            #pragma unroll
            for (int mi = 0; mi < 4; mi++)
                #pragma unroll
                for (int nj = 0; nj < 4; nj++) {
                    int n2 = nj >> 1, od = nj & 1;
                    mma16816(acc[mi][nj], afr[mi], bfr[n2][od], bfr[n2][od + 2]);
                }
        }
        __syncthreads();
        if (c + STAGES < NCHUNK) {
            uint32_t sb2 = dynb + (uint32_t)(c % STAGES) * 32768u;
            #pragma unroll
            for (int q = 0; q < 4; q++) {
                CP_ASYNC16(sb2 + dA[q], gA + (c + STAGES) * 128 + q * 16);
                CP_ASYNC16(sb2 + dB[q], gB + (c + STAGES) * 128 + q * 16);
            }
        }
        CP_COMMIT();
    }

    // ---- epilogue: masked argmax of sq[cand] - 2*dot, both orientations ----
    unsigned long long* redA = (unsigned long long*)dsm;            // [128][4]
    unsigned long long* redB = (unsigned long long*)(dsm + 4096);   // [128][2]
    int tg = lane >> 2, tp = lane & 3;

    // A: anchors = i-tile rows, candidates = j-tile cols
    #pragma unroll
    for (int mi = 0; mi < 4; mi++)
        #pragma unroll
        for (int h = 0; h < 2; h++) {
            int row = wm * 64 + mi * 16 + tg + h * 8;
            int li = s_li[row];
            unsigned long long best = 0ull;
            #pragma unroll
            for (int nj = 0; nj < 4; nj++)
                #pragma unroll
                for (int c2 = 0; c2 < 2; c2++) {
                    int col = wn * 32 + nj * 8 + tp * 2 + c2;
                    if (s_lj[col] != li) {
                        float v = s_sqj[col] - 2.0f * acc[mi][nj][h * 2 + c2];
                        unsigned long long key =
                            ((unsigned long long)f2o(v) << 32) |
                            (unsigned long long)(0xFFFFFFFFu - (unsigned)(j0 + col));
                        if (key > best) best = key;
                    }
                }
            #pragma unroll
            for (int o = 1; o <= 2; o <<= 1) {
                unsigned long long ot = __shfl_xor_sync(0xFFFFFFFFu, best, o);
                if (ot > best) best = ot;
            }
            if (tp == 0) redA[row * 4 + wn] = best;
        }
    __syncthreads();
    if (t < 128) {
        unsigned long long b = redA[t * 4];
        #pragma unroll
        for (int q = 1; q < 4; q++) if (redA[t * 4 + q] > b) b = redA[t * 4 + q];
        if (b) atomicMax(&g_hard_key[i0 + t], b);
    }

    if (bi != bj) {
        // B: anchors = j-tile cols, candidates = i-tile rows
        #pragma unroll
        for (int nj = 0; nj < 4; nj++)
            #pragma unroll
            for (int c2 = 0; c2 < 2; c2++) {
                int col = wn * 32 + nj * 8 + tp * 2 + c2;
                int lj = s_lj[col];
                unsigned long long best = 0ull;
                #pragma unroll
                for (int mi = 0; mi < 4; mi++)
                    #pragma unroll
                    for (int h = 0; h < 2; h++) {
                        int row = wm * 64 + mi * 16 + tg + h * 8;
                        if (s_li[row] != lj) {
                            float v = s_sqi[row] - 2.0f * acc[mi][nj][h * 2 + c2];
                            unsigned long long key =
                                ((unsigned long long)f2o(v) << 32) |
                                (unsigned long long)(0xFFFFFFFFu - (unsigned)(i0 + row));
                            if (key > best) best = key;
                        }
                    }
                #pragma unroll
                for (int o = 4; o <= 16; o <<= 1) {
                    unsigned long long ot = __shfl_xor_sync(0xFFFFFFFFu, best, o);
                    if (ot > best) best = ot;
                }
                if (tg == 0) redB[col * 2 + wm] = best;
            }
        __syncthreads();
        if (t < 128) {
            unsigned long long b = redB[t * 2];
            if (redB[t * 2 + 1] > b) b = redB[t * 2 + 1];
            if (b) atomicMax(&g_hard_key[j0 + t], b);
        }
    }
}

// ---------------- K3: JAX gumbel argmax (integer, monotone shortcut) -------
__global__ void k_rand(const int* __restrict__ label) {
    int i = blockIdx.x;                 // 0..2047
    int t = threadIdx.x;                // 256
    __shared__ int slab[BSZ];           // 16 KB
    for (int j = t; j < BSZ; j += 256) slab[j] = label[j];
    __syncthreads();
    int li0 = slab[i], li1 = slab[i + 2048];

    unsigned long long b0 = 0ull, b1 = 0ull;
    for (int j = t; j < BSZ; j += 256) {
        unsigned int m0 = (unsigned)(i * BSZ + j);
        unsigned int o0, o1;
        threefry2x32(0u, 42u, m0, m0 + HALF_N, o0, o1);
        unsigned long long tb = (unsigned long long)(0xFFFFFFFFu - (unsigned)j);
        if (slab[j] != li0) {
            unsigned long long key = ((unsigned long long)(o0 >> 9) << 32) | tb;
            if (key > b0) b0 = key;
        }
        if (slab[j] != li1) {
            unsigned long long key = ((unsigned long long)(o1 >> 9) << 32) | tb;
            if (key > b1) b1 = key;
        }
    }
    __shared__ unsigned long long r0[256], r1[256];
    r0[t] = b0; r1[t] = b1;
    __syncthreads();
    for (int s = 128; s; s >>= 1) {
        if (t < s) {
            if (r0[t + s] > r0[t]) r0[t] = r0[t + s];
            if (r1[t + s] > r1[t]) r1[t] = r1[t + s];
        }
        __syncthreads();
    }
    if (t == 0) {
        g_rand_idx[i]        = (int)(0xFFFFFFFFu - (unsigned)(r0[0] & 0xFFFFFFFFu)) & (BSZ - 1);
        g_rand_idx[i + 2048] = (int)(0xFFFFFFFFu - (unsigned)(r1[0] & 0xFFFFFFFFu)) & (BSZ - 1);
    }
}

// ---------------- K4: gathered dots + 3-way log-softmax -------------------
__global__ void k_nce(const float* __restrict__ outs,
                      const float* __restrict__ centers,
                      const int* __restrict__ label) {
    int i = blockIdx.x;
    int t = threadIdx.x;                 // 128
    int lab = label[i];
    unsigned long long hk = g_hard_key[i];
    int hidx = (int)(0xFFFFFFFFu - (unsigned)(hk & 0xFFFFFFFFu)) & (BSZ - 1);
    int ridx = g_rand_idx[i] & (BSZ - 1);

    const float4* xi = (const float4*)(outs + (size_t)i * CSZ);
    const float4* pc = (const float4*)(centers + (size_t)lab * CSZ);
    const float4* xr = (const float4*)(outs + (size_t)ridx * CSZ);
    const float4* xh = (const float4*)(outs + (size_t)hidx * CSZ);

    float sp = 0.f, sr = 0.f, sh = 0.f;
    #pragma unroll
    for (int q = t; q < CSZ / 4; q += 128) {
        float4 a = xi[q]; float4 p = pc[q]; float4 r = xr[q]; float4 h = xh[q];
        sp += a.x * p.x + a.y * p.y + a.z * p.z + a.w * p.w;
        sr += a.x * r.x + a.y * r.y + a.z * r.z + a.w * r.w;
        sh += a.x * h.x + a.y * h.y + a.z * h.z + a.w * h.w;
    }
    #pragma unroll
    for (int o = 16; o; o >>= 1) {
        sp += __shfl_xor_sync(0xFFFFFFFFu, sp, o);
        sr += __shfl_xor_sync(0xFFFFFFFFu, sr, o);
        sh += __shfl_xor_sync(0xFFFFFFFFu, sh, o);
    }
    __shared__ float ap[4], ar[4], ah[4];
    int w = t >> 5, l = t & 31;
    if (l == 0) { ap[w] = sp; ar[w] = sr; ah[w] = sh; }
    __syncthreads();
    if (t == 0) {
        float P = ap[0] + ap[1] + ap[2] + ap[3];
        float R = ar[0] + ar[1] + ar[2] + ar[3];
        float H = ah[0] + ah[1] + ah[2] + ah[3];
        float m = fmaxf(P, fmaxf(R, H));
        float lse = logf(expf(P - m) + expf(R - m) + expf(H - m)) + m;
        g_row_nce[i] = lse - P;
    }
}

// ---------------- K5: final deterministic reduce --------------------------
__global__ void k_final(float* __restrict__ out) {
    int t = threadIdx.x;                 // 256
    float a = 0.f, b = 0.f;
    for (int i = t; i < BSZ; i += 256) { a += g_row_ce[i]; b += g_row_nce[i]; }
    __shared__ float s1[256], s2[256];
    s1[t] = a; s2[t] = b;
    __syncthreads();
    for (int s = 128; s; s >>= 1) {
        if (t < s) { s1[t] += s1[t + s]; s2[t] += s2[t + s]; }
        __syncthreads();
    }
    if (t == 0)
        out[0] = s1[0] / (float)BSZ + 0.1f * (s2[0] / (float)BSZ);
}

// ---------------- launch ---------------------------------------------------
extern "C" void kernel_launch(void* const* d_in, const int* in_sizes, int n_in,
                              void* d_out, int out_size) {
    const float* outs    = (const float*)d_in[0];
    const float* centers = (const float*)d_in[1];
    const int*   label   = (const int*)d_in[2];

    cudaFuncSetAttribute(k_hard_hmma, cudaFuncAttributeMaxDynamicSharedMemorySize, 98304);

    k_init<<<(BSZ + 255) / 256, 256>>>();
    k_cvt<<<BSZ * CSZ / 4 / 256, 256>>>(outs);
    k_row_stats<<<BSZ, 256>>>(outs, label);
    k_rand<<<BSZ / 2, 256>>>(label);
    k_hard_hmma<<<NT * (NT + 1) / 2, 256, 98304>>>(label);
    k_nce<<<BSZ, 128>>>(outs, centers, label);
    k_final<<<1, 256>>>((float*)d_out);
}

// round 4
// speedup vs baseline: 4.2326x; 1.1011x over previous
#include <cuda_runtime.h>
#include <cuda_bf16.h>
#include <cstdint>

#define BSZ 4096
#define CSZ 1024
#define NT  32          // 4096 / 128 tiles
#define HALF_N 8388608u // (4096*4096)/2
#define NCHUNK 16       // K = 1024 bf16 / 64 per chunk
#define STAGES 3

// ---------------- scratch (no allocations allowed) ----------------
__device__ float               g_sq[BSZ];
__device__ float               g_row_ce[BSZ];
__device__ float               g_row_nce[BSZ];
__device__ unsigned long long  g_hard_key[BSZ];
__device__ int                 g_rand_idx[BSZ];
__device__ __nv_bfloat16       g_xb16[BSZ * CSZ];   // bf16 copy of outs, 8 MB

// orderable encoding of float for integer max
__device__ __forceinline__ unsigned int f2o(float f) {
    unsigned int u = __float_as_uint(f);
    return (u & 0x80000000u) ? ~u : (u | 0x80000000u);
}

// ---------------- warp MMA helpers (non-'a' PTX only) ----------------
__device__ __forceinline__ uint32_t smem_u32(const void* p) {
    uint32_t a;
    asm("{ .reg .u64 t; cvta.to.shared.u64 t, %1; cvt.u32.u64 %0, t; }" : "=r"(a) : "l"(p));
    return a;
}
__device__ __forceinline__ void ldm_x4(uint32_t* r, uint32_t addr) {
    asm volatile("ldmatrix.sync.aligned.m8n8.x4.shared.b16 {%0,%1,%2,%3}, [%4];"
                 : "=r"(r[0]), "=r"(r[1]), "=r"(r[2]), "=r"(r[3]) : "r"(addr));
}
__device__ __forceinline__ void mma16816(float* c, const uint32_t* a,
                                         uint32_t b0, uint32_t b1) {
    asm volatile("mma.sync.aligned.m16n8k16.row.col.f32.bf16.bf16.f32 "
                 "{%0,%1,%2,%3}, {%4,%5,%6,%7}, {%8,%9}, {%0,%1,%2,%3};"
                 : "+f"(c[0]), "+f"(c[1]), "+f"(c[2]), "+f"(c[3])
                 : "r"(a[0]), "r"(a[1]), "r"(a[2]), "r"(a[3]), "r"(b0), "r"(b1));
}
#define CP_ASYNC16(dst, src) \
    asm volatile("cp.async.cg.shared.global [%0], [%1], 16;" :: "r"(dst), "l"(src))
#define CP_COMMIT() asm volatile("cp.async.commit_group;")
#define CP_WAIT2()  asm volatile("cp.async.wait_group 2;" ::: "memory")

// JAX Threefry-2x32 (20 rounds), key = (0, 42) for jax.random.key(42)
__device__ __forceinline__ void threefry2x32(unsigned int k0, unsigned int k1,
                                             unsigned int x0, unsigned int x1,
                                             unsigned int& o0, unsigned int& o1) {
    unsigned int ks2 = k0 ^ k1 ^ 0x1BD11BDAu;
#define TF_RND(r) { x0 += x1; x1 = (x1 << (r)) | (x1 >> (32 - (r))); x1 ^= x0; }
    x0 += k0;  x1 += k1;
    TF_RND(13) TF_RND(15) TF_RND(26) TF_RND(6)
    x0 += k1;  x1 += ks2 + 1u;
    TF_RND(17) TF_RND(29) TF_RND(16) TF_RND(24)
    x0 += ks2; x1 += k0 + 2u;
    TF_RND(13) TF_RND(15) TF_RND(26) TF_RND(6)
    x0 += k0;  x1 += k1 + 3u;
    TF_RND(17) TF_RND(29) TF_RND(16) TF_RND(24)
    x0 += k1;  x1 += ks2 + 4u;
    TF_RND(13) TF_RND(15) TF_RND(26) TF_RND(6)
    x0 += ks2; x1 += k0 + 5u;
#undef TF_RND
    o0 = x0; o1 = x1;
}

// ---------------- K_prep: init + bf16 cvt + row stats (fused) --------------
__global__ void k_prep(const float* __restrict__ outs,
                       const int* __restrict__ label) {
    int row = blockIdx.x;
    int t = threadIdx.x;            // 256 threads, 4 floats each
    float4 v = ((const float4*)(outs + (size_t)row * CSZ))[t];

    // bf16 convert + store
    __nv_bfloat162 p0 = __floats2bfloat162_rn(v.x, v.y);
    __nv_bfloat162 p1 = __floats2bfloat162_rn(v.z, v.w);
    uint2 o; o.x = *(unsigned*)&p0; o.y = *(unsigned*)&p1;
    ((uint2*)g_xb16)[(size_t)row * 256 + t] = o;

    float mx = fmaxf(fmaxf(v.x, v.y), fmaxf(v.z, v.w));
    #pragma unroll
    for (int q = 16; q; q >>= 1) mx = fmaxf(mx, __shfl_xor_sync(0xFFFFFFFFu, mx, q));
    __shared__ float sm[8];
    int w = t >> 5, l = t & 31;
    if (l == 0) sm[w] = mx;
    __syncthreads();
    if (t == 0) {
        float m = sm[0];
        #pragma unroll
        for (int q = 1; q < 8; q++) m = fmaxf(m, sm[q]);
        sm[0] = m;
    }
    __syncthreads();
    mx = sm[0];

    float es = expf(v.x - mx) + expf(v.y - mx) + expf(v.z - mx) + expf(v.w - mx);
    float qs = v.x * v.x + v.y * v.y + v.z * v.z + v.w * v.w;
    #pragma unroll
    for (int q = 16; q; q >>= 1) {
        es += __shfl_xor_sync(0xFFFFFFFFu, es, q);
        qs += __shfl_xor_sync(0xFFFFFFFFu, qs, q);
    }
    __shared__ float se[8], sq2[8];
    if (l == 0) { se[w] = es; sq2[w] = qs; }
    __syncthreads();
    if (t == 0) {
        float E = 0.f, Q = 0.f;
        #pragma unroll
        for (int q = 0; q < 8; q++) { E += se[q]; Q += sq2[q]; }
        int lab = label[row];
        g_row_ce[row] = logf(E) + mx - outs[(size_t)row * CSZ + lab];
        g_sq[row] = Q;
        g_hard_key[row] = 0ull;
    }
}

// ---------------- K2: symmetric Gram via bf16 HMMA + hard-negative argmax --
extern __shared__ __align__(1024) unsigned char dsm[];  // 96 KB

__global__ __launch_bounds__(256, 2)
void k_hard_hmma(const int* __restrict__ label) {
    int p = blockIdx.x;
    int bi = 0, rem = p, width = NT;
    while (rem >= width) { rem -= width; bi++; width--; }
    int bj = bi + rem;
    int i0 = bi * 128, j0 = bj * 128;

    __shared__ int   s_li[128], s_lj[128];
    __shared__ float s_sqi[128], s_sqj[128];

    int t = threadIdx.x;
    int lane = t & 31, wid = t >> 5;
    int wm = wid & 1, wn = wid >> 1;
    uint32_t dynb = smem_u32(dsm);

    if (t < 128) {
        s_li[t] = label[i0 + t]; s_sqi[t] = g_sq[i0 + t];
        s_lj[t] = label[j0 + t]; s_sqj[t] = g_sq[j0 + t];
    }

    int lrow = t >> 1;
    int lseg = (t & 1) * 4;
    const char* gA = (const char*)g_xb16 + (size_t)(i0 + lrow) * 2048 + lseg * 16;
    const char* gB = (const char*)g_xb16 + (size_t)(j0 + lrow) * 2048 + lseg * 16;
    uint32_t dA[4], dB[4];
    #pragma unroll
    for (int q = 0; q < 4; q++) {
        unsigned off = (unsigned)lrow * 128u + (unsigned)(lseg + q) * 16u;
        unsigned sw = off ^ ((off >> 3) & 0x70u);
        dA[q] = sw; dB[q] = sw + 16384u;
    }

    #pragma unroll
    for (int s = 0; s < STAGES; s++) {
        uint32_t sb = dynb + s * 32768u;
        #pragma unroll
        for (int q = 0; q < 4; q++) {
            CP_ASYNC16(sb + dA[q], gA + s * 128 + q * 16);
            CP_ASYNC16(sb + dB[q], gB + s * 128 + q * 16);
        }
        CP_COMMIT();
    }

    float acc[4][4][4];
    #pragma unroll
    for (int a = 0; a < 4; a++)
        #pragma unroll
        for (int b = 0; b < 4; b++)
            #pragma unroll
            for (int c = 0; c < 4; c++) acc[a][b][c] = 0.f;

    int rowA0 = wm * 64 + (lane & 15);
    int rowB0 = wn * 32 + (lane & 15);
    int kb_l  = (lane & 16);

    for (int c = 0; c < NCHUNK; c++) {
        CP_WAIT2();
        __syncthreads();
        uint32_t sb = dynb + (uint32_t)(c % STAGES) * 32768u;
        #pragma unroll
        for (int ks = 0; ks < 4; ks++) {
            uint32_t afr[4][4], bfr[2][4];
            #pragma unroll
            for (int mi = 0; mi < 4; mi++) {
                unsigned off = (unsigned)(rowA0 + mi * 16) * 128u + (unsigned)(ks * 32 + kb_l);
                unsigned sw = off ^ ((off >> 3) & 0x70u);
                ldm_x4(afr[mi], sb + sw);
            }
            #pragma unroll
            for (int n2 = 0; n2 < 2; n2++) {
                unsigned off = (unsigned)(rowB0 + n2 * 16) * 128u + (unsigned)(ks * 32 + kb_l);
                unsigned sw = off ^ ((off >> 3) & 0x70u);
                ldm_x4(bfr[n2], sb + 16384u + sw);
            }
            #pragma unroll
            for (int mi = 0; mi < 4; mi++)
                #pragma unroll
                for (int nj = 0; nj < 4; nj++) {
                    int n2 = nj >> 1, od = nj & 1;
                    mma16816(acc[mi][nj], afr[mi], bfr[n2][od], bfr[n2][od + 2]);
                }
        }
        __syncthreads();
        if (c + STAGES < NCHUNK) {
            uint32_t sb2 = dynb + (uint32_t)(c % STAGES) * 32768u;
            #pragma unroll
            for (int q = 0; q < 4; q++) {
                CP_ASYNC16(sb2 + dA[q], gA + (c + STAGES) * 128 + q * 16);
                CP_ASYNC16(sb2 + dB[q], gB + (c + STAGES) * 128 + q * 16);
            }
        }
        CP_COMMIT();
    }

    // ---- epilogue: masked argmax of sq[cand] - 2*dot, both orientations ----
    unsigned long long* redA = (unsigned long long*)dsm;            // [128][4]
    unsigned long long* redB = (unsigned long long*)(dsm + 4096);   // [128][2]
    int tg = lane >> 2, tp = lane & 3;

    #pragma unroll
    for (int mi = 0; mi < 4; mi++)
        #pragma unroll
        for (int h = 0; h < 2; h++) {
            int row = wm * 64 + mi * 16 + tg + h * 8;
            int li = s_li[row];
            unsigned long long best = 0ull;
            #pragma unroll
            for (int nj = 0; nj < 4; nj++)
                #pragma unroll
                for (int c2 = 0; c2 < 2; c2++) {
                    int col = wn * 32 + nj * 8 + tp * 2 + c2;
                    if (s_lj[col] != li) {
                        float v = s_sqj[col] - 2.0f * acc[mi][nj][h * 2 + c2];
                        unsigned long long key =
                            ((unsigned long long)f2o(v) << 32) |
                            (unsigned long long)(0xFFFFFFFFu - (unsigned)(j0 + col));
                        if (key > best) best = key;
                    }
                }
            #pragma unroll
            for (int o = 1; o <= 2; o <<= 1) {
                unsigned long long ot = __shfl_xor_sync(0xFFFFFFFFu, best, o);
                if (ot > best) best = ot;
            }
            if (tp == 0) redA[row * 4 + wn] = best;
        }
    __syncthreads();
    if (t < 128) {
        unsigned long long b = redA[t * 4];
        #pragma unroll
        for (int q = 1; q < 4; q++) if (redA[t * 4 + q] > b) b = redA[t * 4 + q];
        if (b) atomicMax(&g_hard_key[i0 + t], b);
    }

    if (bi != bj) {
        #pragma unroll
        for (int nj = 0; nj < 4; nj++)
            #pragma unroll
            for (int c2 = 0; c2 < 2; c2++) {
                int col = wn * 32 + nj * 8 + tp * 2 + c2;
                int lj = s_lj[col];
                unsigned long long best = 0ull;
                #pragma unroll
                for (int mi = 0; mi < 4; mi++)
                    #pragma unroll
                    for (int h = 0; h < 2; h++) {
                        int row = wm * 64 + mi * 16 + tg + h * 8;
                        if (s_li[row] != lj) {
                            float v = s_sqi[row] - 2.0f * acc[mi][nj][h * 2 + c2];
                            unsigned long long key =
                                ((unsigned long long)f2o(v) << 32) |
                                (unsigned long long)(0xFFFFFFFFu - (unsigned)(i0 + row));
                            if (key > best) best = key;
                        }
                    }
                #pragma unroll
                for (int o = 4; o <= 16; o <<= 1) {
                    unsigned long long ot = __shfl_xor_sync(0xFFFFFFFFu, best, o);
                    if (ot > best) best = ot;
                }
                if (tg == 0) redB[col * 2 + wm] = best;
            }
        __syncthreads();
        if (t < 128) {
            unsigned long long b = redB[t * 2];
            if (redB[t * 2 + 1] > b) b = redB[t * 2 + 1];
            if (b) atomicMax(&g_hard_key[j0 + t], b);
        }
    }
}

// ---------------- K3: JAX gumbel argmax (integer, monotone shortcut) -------
__global__ void k_rand(const int* __restrict__ label) {
    int i = blockIdx.x;                 // 0..2047
    int t = threadIdx.x;                // 256
    __shared__ int slab[BSZ];           // 16 KB
    for (int j = t; j < BSZ; j += 256) slab[j] = label[j];
    __syncthreads();
    int li0 = slab[i], li1 = slab[i + 2048];

    // 32-bit best + index; strict > with ascending j keeps first occurrence
    unsigned best0 = 0u, best1 = 0u;
    int bj0 = BSZ - 1, bj1 = BSZ - 1;
    for (int j = t; j < BSZ; j += 256) {
        unsigned int m0 = (unsigned)(i * BSZ + j);
        unsigned int o0, o1;
        threefry2x32(0u, 42u, m0, m0 + HALF_N, o0, o1);
        unsigned b0 = o0 >> 9, b1 = o1 >> 9;
        int lj = slab[j];
        if (lj != li0 && b0 > best0) { best0 = b0; bj0 = j; }
        if (lj != li1 && b1 > best1) { best1 = b1; bj1 = j; }
    }
    __shared__ unsigned long long r0[256], r1[256];
    r0[t] = ((unsigned long long)best0 << 32) | (unsigned long long)(0xFFFFFFFFu - (unsigned)bj0);
    r1[t] = ((unsigned long long)best1 << 32) | (unsigned long long)(0xFFFFFFFFu - (unsigned)bj1);
    __syncthreads();
    for (int s = 128; s; s >>= 1) {
        if (t < s) {
            if (r0[t + s] > r0[t]) r0[t] = r0[t + s];
            if (r1[t + s] > r1[t]) r1[t] = r1[t + s];
        }
        __syncthreads();
    }
    if (t == 0) {
        g_rand_idx[i]        = (int)(0xFFFFFFFFu - (unsigned)(r0[0] & 0xFFFFFFFFu)) & (BSZ - 1);
        g_rand_idx[i + 2048] = (int)(0xFFFFFFFFu - (unsigned)(r1[0] & 0xFFFFFFFFu)) & (BSZ - 1);
    }
}

// ---------------- K4: gathered dots + 3-way log-softmax -------------------
__global__ void k_nce(const float* __restrict__ outs,
                      const float* __restrict__ centers,
                      const int* __restrict__ label) {
    int i = blockIdx.x;
    int t = threadIdx.x;                 // 128
    int lab = label[i];
    unsigned long long hk = g_hard_key[i];
    int hidx = (int)(0xFFFFFFFFu - (unsigned)(hk & 0xFFFFFFFFu)) & (BSZ - 1);
    int ridx = g_rand_idx[i] & (BSZ - 1);

    const float4* xi = (const float4*)(outs + (size_t)i * CSZ);
    const float4* pc = (const float4*)(centers + (size_t)lab * CSZ);
    const float4* xr = (const float4*)(outs + (size_t)ridx * CSZ);
    const float4* xh = (const float4*)(outs + (size_t)hidx * CSZ);

    float sp = 0.f, sr = 0.f, sh = 0.f;
    #pragma unroll
    for (int q = t; q < CSZ / 4; q += 128) {
        float4 a = xi[q]; float4 p = pc[q]; float4 r = xr[q]; float4 h = xh[q];
        sp += a.x * p.x + a.y * p.y + a.z * p.z + a.w * p.w;
        sr += a.x * r.x + a.y * r.y + a.z * r.z + a.w * r.w;
        sh += a.x * h.x + a.y * h.y + a.z * h.z + a.w * h.w;
    }
    #pragma unroll
    for (int o = 16; o; o >>= 1) {
        sp += __shfl_xor_sync(0xFFFFFFFFu, sp, o);
        sr += __shfl_xor_sync(0xFFFFFFFFu, sr, o);
        sh += __shfl_xor_sync(0xFFFFFFFFu, sh, o);
    }
    __shared__ float ap[4], ar[4], ah[4];
    int w = t >> 5, l = t & 31;
    if (l == 0) { ap[w] = sp; ar[w] = sr; ah[w] = sh; }
    __syncthreads();
    if (t == 0) {
        float P = ap[0] + ap[1] + ap[2] + ap[3];
        float R = ar[0] + ar[1] + ar[2] + ar[3];
        float H = ah[0] + ah[1] + ah[2] + ah[3];
        float m = fmaxf(P, fmaxf(R, H));
        float lse = logf(expf(P - m) + expf(R - m) + expf(H - m)) + m;
        g_row_nce[i] = lse - P;
    }
}

// ---------------- K5: final deterministic reduce --------------------------
__global__ void k_final(float* __restrict__ out) {
    int t = threadIdx.x;                 // 256
    float a = 0.f, b = 0.f;
    for (int i = t; i < BSZ; i += 256) { a += g_row_ce[i]; b += g_row_nce[i]; }
    __shared__ float s1[256], s2[256];
    s1[t] = a; s2[t] = b;
    __syncthreads();
    for (int s = 128; s; s >>= 1) {
        if (t < s) { s1[t] += s1[t + s]; s2[t] += s2[t + s]; }
        __syncthreads();
    }
    if (t == 0)
        out[0] = s1[0] / (float)BSZ + 0.1f * (s2[0] / (float)BSZ);
}

// ---------------- launch ---------------------------------------------------
extern "C" void kernel_launch(void* const* d_in, const int* in_sizes, int n_in,
                              void* d_out, int out_size) {
    const float* outs    = (const float*)d_in[0];
    const float* centers = (const float*)d_in[1];
    const int*   label   = (const int*)d_in[2];

    // one-time resource init (host objects only; no device allocations)
    static cudaStream_t s2 = nullptr;
    static cudaEvent_t ev_fork = nullptr, ev_join = nullptr;
    static bool attr_done = false;
    if (!s2) {
        cudaStreamCreateWithFlags(&s2, cudaStreamNonBlocking);
        cudaEventCreateWithFlags(&ev_fork, cudaEventDisableTiming);
        cudaEventCreateWithFlags(&ev_join, cudaEventDisableTiming);
    }
    if (!attr_done) {
        cudaFuncSetAttribute(k_hard_hmma, cudaFuncAttributeMaxDynamicSharedMemorySize, 98304);
        attr_done = true;
    }

    // fork: k_rand (label-only dependency) runs concurrently with prep+hard
    cudaEventRecord(ev_fork, 0);
    cudaStreamWaitEvent(s2, ev_fork, 0);
    k_rand<<<BSZ / 2, 256, 0, s2>>>(label);
    cudaEventRecord(ev_join, s2);

    k_prep<<<BSZ, 256>>>(outs, label);
    k_hard_hmma<<<NT * (NT + 1) / 2, 256, 98304>>>(label);

    // join
    cudaStreamWaitEvent(0, ev_join, 0);
    k_nce<<<BSZ, 128>>>(outs, centers, label);
    k_final<<<1, 256>>>((float*)d_out);
}